// round 17
// baseline (speedup 1.0000x reference)
#include <cuda_runtime.h>
#include <cuda_bf16.h>
#include <cuda_fp16.h>
#include <math.h>
#include <stdint.h>

#define BATCH 4
#define CDIM  256
#define HW    2304          // n = 48*48
#define MROWS (BATCH*HW)    // 9216
#define NHEAD 8
#define DHEAD 32

typedef unsigned long long u64;
typedef unsigned int u32;
typedef unsigned short u16;

// Scratch (static device memory). All inter-kernel tensors single fp16.
__device__ __align__(16) u16 g_xsh[MROWS*CDIM];   // xs fp16
__device__ __align__(16) u16 g_qh[MROWS*CDIM];    // Q fp16 (scaled by log2e/sqrt(32))
__device__ __align__(16) u16 g_kh[MROWS*CDIM];    // K fp16
__device__ __align__(16) u16 g_vh[MROWS*CDIM];    // V fp16
__device__ __align__(16) u16 g_aoh[MROWS*CDIM];   // attn out fp16
__device__ __align__(16) u16 g_wh[4*CDIM*CDIM];   // weights fp16

// ---------------------------------------------------------------------------
// helpers
// ---------------------------------------------------------------------------
__device__ __forceinline__ u32 hf2(float x0, float x1) {
    u32 r; asm("cvt.rn.f16x2.f32 %0, %1, %2;" : "=r"(r) : "f"(x1), "f"(x0));
    return r;
}
__device__ __forceinline__ u32 ex2h2(u32 v) {
    u32 r; asm("ex2.approx.f16x2 %0, %1;" : "=r"(r) : "r"(v));
    return r;
}
__device__ __forceinline__ u32 hadd2(u32 a, u32 b) {
    u32 r; asm("add.rn.f16x2 %0, %1, %2;" : "=r"(r) : "r"(a), "r"(b));
    return r;
}
__device__ __forceinline__ float2 h22f2(u32 v) {
    __half2 h = *(__half2*)&v;
    return __half22float2(h);
}
__device__ __forceinline__ void mma16816h(float d[4], const u32 a[4], u32 b0, u32 b1) {
    asm volatile("mma.sync.aligned.m16n8k16.row.col.f32.f16.f16.f32 "
        "{%0,%1,%2,%3}, {%4,%5,%6,%7}, {%8,%9}, {%0,%1,%2,%3};"
        : "+f"(d[0]), "+f"(d[1]), "+f"(d[2]), "+f"(d[3])
        : "r"(a[0]), "r"(a[1]), "r"(a[2]), "r"(a[3]), "r"(b0), "r"(b1));
}
// fp16-accumulator MMA: D (2x u32 = 4 halves) += A*B
__device__ __forceinline__ void mma16816hh(u32* d, const u32 a[4], u32 b0, u32 b1) {
    asm volatile("mma.sync.aligned.m16n8k16.row.col.f16.f16.f16.f16 "
        "{%0,%1}, {%2,%3,%4,%5}, {%6,%7}, {%0,%1};"
        : "+r"(d[0]), "+r"(d[1])
        : "r"(a[0]), "r"(a[1]), "r"(a[2]), "r"(a[3]), "r"(b0), "r"(b1));
}
__device__ __forceinline__ u32 smem_u32_(const void* p) {
    u32 a; asm("{ .reg .u64 t; cvta.to.shared.u64 t, %1; cvt.u32.u64 %0, t; }"
               : "=r"(a) : "l"(p)); return a;
}
__device__ __forceinline__ void cpa16(u32 dst, const void* src) {
    asm volatile("cp.async.cg.shared.global [%0], [%1], 16;"
                 :: "r"(dst), "l"(src) : "memory");
}
#define CP_COMMIT() asm volatile("cp.async.commit_group;" ::: "memory")
#define CP_WAIT0()  asm volatile("cp.async.wait_group 0;" ::: "memory")
__device__ __forceinline__ void ldmat4(u32 r[4], u32 addr) {
    asm volatile("ldmatrix.sync.aligned.m8n8.x4.shared.b16 {%0,%1,%2,%3}, [%4];"
        : "=r"(r[0]), "=r"(r[1]), "=r"(r[2]), "=r"(r[3]) : "r"(addr));
}
__device__ __forceinline__ void ldmat4t(u32 r[4], u32 addr) {
    asm volatile("ldmatrix.sync.aligned.m8n8.x4.trans.shared.b16 {%0,%1,%2,%3}, [%4];"
        : "=r"(r[0]), "=r"(r[1]), "=r"(r[2]), "=r"(r[3]) : "r"(addr));
}

// ---------------------------------------------------------------------------
// Kernel 0: convert weight matrices to fp16 once (4 x 256x256)
// ---------------------------------------------------------------------------
__global__ void k_split_w(const float* __restrict__ wq, const float* __restrict__ wk,
                          const float* __restrict__ wv, const float* __restrict__ wo)
{
    int idx = blockIdx.x * 256 + threadIdx.x;
    const float* ws[4] = { wq, wk, wv, wo };
    #pragma unroll
    for (int m = 0; m < 4; m++) {
        __half h = __float2half_rn(ws[m][idx]);
        g_wh[m * 65536 + idx] = *(u16*)&h;
    }
}

// ---------------------------------------------------------------------------
// Kernel 1: x [b,c,h,w] -> xs fp16 [b,n,c] transpose + positional encoding
// ---------------------------------------------------------------------------
__global__ void k_transpose_pe(const float* __restrict__ x)
{
    __shared__ float tile[32][33];
    int b  = blockIdx.z;
    int p0 = blockIdx.x * 32;
    int c0 = blockIdx.y * 32;
    int tx = threadIdx.x, ty = threadIdx.y;

    #pragma unroll
    for (int i = 0; i < 4; i++) {
        int cc = c0 + ty + i * 8;
        tile[ty + i * 8][tx] = x[((size_t)(b * CDIM + cc)) * HW + p0 + tx];
    }
    __syncthreads();
    #pragma unroll
    for (int i = 0; i < 4; i++) {
        int p  = p0 + ty + i * 8;
        int cc = c0 + tx;
        float v = tile[tx][ty + i * 8];
        float pe = 0.0f;
        if (p != 0) {
            // 10000^(-2c/256) = exp2(-c * log2(10000)/128)
            float freq = exp2f((float)cc * -0.10381025296523007f);
            float ang = (float)p * freq;
            pe = (cc & 1) ? cosf(ang) : sinf(ang);
        }
        __half hv = __float2half_rn(v + pe);
        g_xsh[((size_t)(b * HW + p)) * CDIM + cc] = *(u16*)&hv;
    }
}

// ---------------------------------------------------------------------------
// Projection GEMM (fp16 1-pass): out = A @ W^T + bias
// Block = 256 thr = 8 warps; tile 128m x 64n; K chunks of 64 double-buffered.
// ---------------------------------------------------------------------------
#define PST   72
#define SA    0
#define SW    9216
#define PSTAGE 13824          // u16 per stage (27648 B); x2 = 55296 B

__device__ __forceinline__ void proj_stage(
    u32 sbase, int buf, int m0, int n0, int k0, int tid,
    const u16* __restrict__ Ag, const u16* __restrict__ Wg)
{
    u32 b0 = sbase + (u32)buf * (PSTAGE * 2);
    #pragma unroll
    for (int it = 0; it < 4; it++) {
        int idx = tid + it * 256;
        int row = idx >> 3, c8 = (idx & 7) * 8;
        size_t gs = (size_t)(m0 + row) * CDIM + k0 + c8;
        cpa16(b0 + SA * 2 + (u32)(row * PST + c8) * 2, Ag + gs);
    }
    #pragma unroll
    for (int it = 0; it < 2; it++) {
        int idx = tid + it * 256;
        int row = idx >> 3, c8 = (idx & 7) * 8;
        size_t gs = (size_t)(n0 + row) * CDIM + k0 + c8;
        cpa16(b0 + SW * 2 + (u32)(row * PST + c8) * 2, Wg + gs);
    }
}

// OUT_MODE: 0 = fp16 (QKV / attn-input), 1 = fp32 transposed (final out)
template<int OUT_MODE>
__device__ __forceinline__ void proj_body(
    const u16* __restrict__ Ag, int widx, const float* __restrict__ bias,
    u16* __restrict__ outh, float* __restrict__ outf, float qs)
{
    extern __shared__ u16 smp[];
    int tid = threadIdx.x;
    int w = tid >> 5, lane = tid & 31;
    int r = lane >> 2, c2 = (lane & 3) * 2;
    int m0 = blockIdx.y * 128, n0 = blockIdx.x * 64;
    u32 sbase = smem_u32_(smp);
    const u16* Wg = g_wh + widx * 65536;

    float o[8][4];
    #pragma unroll
    for (int i = 0; i < 8; i++)
        #pragma unroll
        for (int j = 0; j < 4; j++) o[i][j] = 0.0f;

    proj_stage(sbase, 0, m0, n0, 0, tid, Ag, Wg);
    CP_COMMIT();

    u32 arow = (u32)(w * 16 + (lane & 15));
    u32 acol = (u32)((lane >> 4) << 3);

    for (int c = 0; c < 4; c++) {
        CP_WAIT0();
        __syncthreads();
        if (c < 3) {
            proj_stage(sbase, (c + 1) & 1, m0, n0, (c + 1) * 64, tid, Ag, Wg);
            CP_COMMIT();
        }

        int sb = (c & 1) * PSTAGE;
        const u16* sW = smp + sb + SW;
        u32 abase = sbase + (u32)sb * 2 + (arow * PST + acol) * 2;

        #pragma unroll
        for (int kc = 0; kc < 4; kc++) {
            u32 ah[4];
            ldmat4(ah, abase + (u32)(kc * 16) * 2);
            #pragma unroll
            for (int nc = 0; nc < 8; nc++) {
                int off = (nc * 8 + r) * PST + kc * 16 + c2;
                u32 b0 = *(const u32*)&sW[off];
                u32 b1 = *(const u32*)&sW[off + 8];
                mma16816h(o[nc], ah, b0, b1);
            }
        }
    }

    int mr0 = m0 + w * 16 + r;
    int mr1 = mr0 + 8;
    if (OUT_MODE == 0) {
        size_t r0off = (size_t)mr0 * CDIM + n0;
        size_t r1off = (size_t)mr1 * CDIM + n0;
        #pragma unroll
        for (int nc = 0; nc < 8; nc++) {
            float2 bi = *(const float2*)(bias + n0 + nc * 8 + c2);
            *(u32*)&outh[r0off + nc * 8 + c2] =
                hf2((o[nc][0] + bi.x) * qs, (o[nc][1] + bi.y) * qs);
            *(u32*)&outh[r1off + nc * 8 + c2] =
                hf2((o[nc][2] + bi.x) * qs, (o[nc][3] + bi.y) * qs);
        }
    } else {
        int bb0 = mr0 / HW, pp0 = mr0 % HW;
        int bb1 = mr1 / HW, pp1 = mr1 % HW;
        #pragma unroll
        for (int nc = 0; nc < 8; nc++) {
            float2 bi = *(const float2*)(bias + n0 + nc * 8 + c2);
            int nn = n0 + nc * 8 + c2;
            outf[((size_t)(bb0 * CDIM + nn)) * HW + pp0]     = o[nc][0] + bi.x;
            outf[((size_t)(bb0 * CDIM + nn + 1)) * HW + pp0] = o[nc][1] + bi.y;
            outf[((size_t)(bb1 * CDIM + nn)) * HW + pp1]     = o[nc][2] + bi.x;
            outf[((size_t)(bb1 * CDIM + nn + 1)) * HW + pp1] = o[nc][3] + bi.y;
        }
    }
}

// Q scale folds softmax's log2(e): (1/sqrt(32)) * log2(e)
#define QSCALE 0.25503472316688193f

__global__ void __launch_bounds__(256) k_proj_qkv(
    const float* __restrict__ bq, const float* __restrict__ bk,
    const float* __restrict__ bv)
{
    const float* bias; u16* outh; float qs;
    if (blockIdx.z == 0)      { bias = bq; outh = g_qh; qs = QSCALE; }
    else if (blockIdx.z == 1) { bias = bk; outh = g_kh; qs = 1.0f; }
    else                      { bias = bv; outh = g_vh; qs = 1.0f; }
    proj_body<0>(g_xsh, blockIdx.z, bias, outh, nullptr, qs);
}

__global__ void __launch_bounds__(256) k_proj_out(
    const float* __restrict__ bo, float* __restrict__ out)
{
    proj_body<1>(g_aoh, 3, bo, nullptr, out, 1.0f);
}

// ---------------------------------------------------------------------------
// Kernel 3: flash attention. Block = 128 thr = 4 warps; warp owns 32 queries.
// K-tile = 128 keys staged per sync (two 64-key compute halves, arithmetic
// identical to R16). fp16-acc S, in-place ex2 softmax, fp32 PV accumulators.
// smem: [buf][K,V][128 x 40 halves]; array = 10240 B, buffer = 20480 B.
// ---------------------------------------------------------------------------
#define KST 40
#define NT2 (HW / 128)      // 18 staged tiles

__global__ void __launch_bounds__(128, 4) k_attn_mma()
{
    __shared__ u16 sbuf[2][2][128 * KST];

    int tid = threadIdx.x;
    int w = tid >> 5, lane = tid & 31;
    int r = lane >> 2, c2 = (lane & 3) * 2;
    int b = blockIdx.y >> 3, h = blockIdx.y & 7;
    int q0 = blockIdx.x * 128;
    u32 sb = smem_u32_(&sbuf[0][0][0]);

    // staging: thread covers rows {srow, +32, +64, +96}, 16B chunk each
    int srow = tid >> 2, sch = (tid & 3) * 8;
    size_t gb0 = ((size_t)(b * HW) + srow) * CDIM + h * DHEAD + sch;
    u32 sd0 = sb + (u32)(srow * KST + sch) * 2;

    {   // prologue: stage tile 0 (128 keys of K and V)
        #pragma unroll
        for (int j = 0; j < 4; j++) {
            size_t g = gb0 + (size_t)j * 32 * CDIM;
            u32 d = sd0 + (u32)j * (32 * KST * 2);
            cpa16(d,          g_kh + g);
            cpa16(d + 10240,  g_vh + g);
        }
        CP_COMMIT();
    }

    // Q fragments: two 16-row blocks per warp
    u32 qh[2][2][4];
    #pragma unroll
    for (int qb = 0; qb < 2; qb++) {
        const u16* qhg = g_qh
            + ((size_t)(b * HW + q0 + w * 32 + qb * 16)) * CDIM + h * DHEAD;
        #pragma unroll
        for (int kc = 0; kc < 2; kc++)
            #pragma unroll
            for (int i = 0; i < 4; i++) {
                int rr = r + (i & 1) * 8;
                int cc = kc * 16 + c2 + (i >> 1) * 8;
                qh[qb][kc][i] = *(const u32*)(qhg + (size_t)rr * CDIM + cc);
            }
    }

    float o[2][4][4];
    #pragma unroll
    for (int qb = 0; qb < 2; qb++)
        #pragma unroll
        for (int i = 0; i < 4; i++)
            #pragma unroll
            for (int j = 0; j < 4; j++) o[qb][i][j] = 0.0f;
    float lsum[2][2] = {{0.0f, 0.0f}, {0.0f, 0.0f}};

    // ldmatrix lane addressing
    int vkey = lane & 15;
    int vdim = (lane >> 4) << 3;
    int klrow = ((lane >> 4) << 3) + (lane & 7);
    int kdoff = ((lane >> 3) & 1) * 8;

    for (int kt = 0; kt < NT2; kt++) {
        int buf = kt & 1;
        CP_WAIT0();
        __syncthreads();
        if (kt + 1 < NT2) {
            size_t off = (size_t)(kt + 1) * 128 * CDIM;
            u32 dbase = sd0 + (u32)((kt + 1) & 1) * 20480;
            #pragma unroll
            for (int j = 0; j < 4; j++) {
                size_t g = gb0 + off + (size_t)j * 32 * CDIM;
                u32 d = dbase + (u32)j * (32 * KST * 2);
                cpa16(d,          g_kh + g);
                cpa16(d + 10240,  g_vh + g);
            }
            CP_COMMIT();
        }

        u32 tbase = sb + (u32)buf * 20480;

        // ---- two 64-key halves (same arithmetic as R16 per half) ----
        #pragma unroll
        for (int hb = 0; hb < 2; hb++) {
            u32 kbase = tbase + (u32)hb * 5120;       // K rows hb*64..
            u32 vhb   = tbase + 10240 + (u32)hb * 5120;

            // S in fp16 accumulators: ph = P fragment directly
            u32 ph[2][4][4];
            #pragma unroll
            for (int qb = 0; qb < 2; qb++)
                #pragma unroll
                for (int np = 0; np < 4; np++)
                    #pragma unroll
                    for (int j = 0; j < 4; j++) ph[qb][np][j] = 0;

            #pragma unroll
            for (int kc = 0; kc < 2; kc++)
                #pragma unroll
                for (int np = 0; np < 4; np++) {
                    u32 kb[4];
                    u32 addr = kbase +
                        (u32)(((np * 16 + klrow) * KST) + kc * 16 + kdoff) * 2;
                    ldmat4(kb, addr);
                    mma16816hh(&ph[0][np][0], qh[0][kc], kb[0], kb[1]);
                    mma16816hh(&ph[0][np][2], qh[0][kc], kb[2], kb[3]);
                    mma16816hh(&ph[1][np][0], qh[1][kc], kb[0], kb[1]);
                    mma16816hh(&ph[1][np][2], qh[1][kc], kb[2], kb[3]);
                }

            // softmax: ex2.f16x2 in place; row sums via HADD2
            #pragma unroll
            for (int qb = 0; qb < 2; qb++) {
                u32 acc0 = 0, acc1 = 0;     // rows r / r+8
                #pragma unroll
                for (int np = 0; np < 4; np++) {
                    ph[qb][np][0] = ex2h2(ph[qb][np][0]);
                    ph[qb][np][1] = ex2h2(ph[qb][np][1]);
                    ph[qb][np][2] = ex2h2(ph[qb][np][2]);
                    ph[qb][np][3] = ex2h2(ph[qb][np][3]);
                    acc0 = hadd2(acc0, ph[qb][np][0]);
                    acc0 = hadd2(acc0, ph[qb][np][2]);
                    acc1 = hadd2(acc1, ph[qb][np][1]);
                    acc1 = hadd2(acc1, ph[qb][np][3]);
                }
                float2 a0 = h22f2(acc0), a1 = h22f2(acc1);
                lsum[qb][0] += a0.x + a0.y;
                lsum[qb][1] += a1.x + a1.y;
            }

            // O += P V : V fragments shared across both q-blocks
            #pragma unroll
            for (int kc2 = 0; kc2 < 4; kc2++) {
                u32 a0 = (u32)(((kc2 * 16 + vkey) * KST) + vdim) * 2;
                u32 a1 = a0 + 32;
                u32 vh0[4], vh1[4];
                ldmat4t(vh0, vhb + a0);
                ldmat4t(vh1, vhb + a1);
                mma16816h(o[0][0], ph[0][kc2], vh0[0], vh0[1]);
                mma16816h(o[0][1], ph[0][kc2], vh0[2], vh0[3]);
                mma16816h(o[0][2], ph[0][kc2], vh1[0], vh1[1]);
                mma16816h(o[0][3], ph[0][kc2], vh1[2], vh1[3]);
                mma16816h(o[1][0], ph[1][kc2], vh0[0], vh0[1]);
                mma16816h(o[1][1], ph[1][kc2], vh0[2], vh0[3]);
                mma16816h(o[1][2], ph[1][kc2], vh1[0], vh1[1]);
                mma16816h(o[1][3], ph[1][kc2], vh1[2], vh1[3]);
            }
        }
    }

    // ---- epilogue: single fp16 output ----
    #pragma unroll
    for (int qb = 0; qb < 2; qb++) {
        float l0 = lsum[qb][0], l1 = lsum[qb][1];
        l0 += __shfl_xor_sync(0xffffffffu, l0, 1);
        l0 += __shfl_xor_sync(0xffffffffu, l0, 2);
        l1 += __shfl_xor_sync(0xffffffffu, l1, 1);
        l1 += __shfl_xor_sync(0xffffffffu, l1, 2);
        float inv0 = 1.0f / l0, inv1 = 1.0f / l1;

        int row0 = q0 + w * 32 + qb * 16 + r;
        size_t o0 = ((size_t)(b * HW + row0)) * CDIM + h * DHEAD;
        size_t o1 = o0 + 8 * CDIM;
        #pragma unroll
        for (int nc2 = 0; nc2 < 4; nc2++) {
            *(u32*)&g_aoh[o0 + nc2 * 8 + c2] =
                hf2(o[qb][nc2][0] * inv0, o[qb][nc2][1] * inv0);
            *(u32*)&g_aoh[o1 + nc2 * 8 + c2] =
                hf2(o[qb][nc2][2] * inv1, o[qb][nc2][3] * inv1);
        }
    }
}

// ---------------------------------------------------------------------------
extern "C" void kernel_launch(void* const* d_in, const int* in_sizes, int n_in,
                              void* d_out, int out_size)
{
    const float* x  = (const float*)d_in[0];
    const float* wq = (const float*)d_in[1];
    const float* bq = (const float*)d_in[2];
    const float* wk = (const float*)d_in[3];
    const float* bk = (const float*)d_in[4];
    const float* wv = (const float*)d_in[5];
    const float* bv = (const float*)d_in[6];
    const float* wo = (const float*)d_in[7];
    const float* bo = (const float*)d_in[8];

    const int PROJ_SMEM = PSTAGE * 2 * 2;   // 55296 bytes
    cudaFuncSetAttribute(k_proj_qkv, cudaFuncAttributeMaxDynamicSharedMemorySize, PROJ_SMEM);
    cudaFuncSetAttribute(k_proj_out, cudaFuncAttributeMaxDynamicSharedMemorySize, PROJ_SMEM);

    {   // 0) weights -> fp16 once
        k_split_w<<<256, 256>>>(wq, wk, wv, wo);
    }
    {   // 1) transpose + positional encoding -> fp16 xs
        dim3 blk(32, 8);
        dim3 grd(HW / 32, CDIM / 32, BATCH);
        k_transpose_pe<<<grd, blk>>>(x);
    }
    {   // 2) QKV projections (fp16 1-pass)
        dim3 grd(CDIM / 64, MROWS / 128, 3);
        k_proj_qkv<<<grd, 256, PROJ_SMEM>>>(bq, bk, bv);
    }
    {   // 3) flash attention (128-key staged tiles)
        dim3 grd(HW / 128, BATCH * NHEAD);
        k_attn_mma<<<grd, 128>>>();
    }
    {   // 4) output projection (fp16 1-pass) + transpose to [b,c,h,w]
        dim3 grd(CDIM / 64, MROWS / 128);
        k_proj_out<<<grd, 256, PROJ_SMEM>>>(bo, (float*)d_out);
    }
}